// round 13
// baseline (speedup 1.0000x reference)
#include <cuda_runtime.h>
#include <cstdint>

// Problem constants (match reference)
#define BOX   120
#define VOL   (BOX * BOX * BOX)       // 1,728,000
#define NTYPE 11
#define BATCH 4
#define BT    (BATCH * NTYPE)         // 44
#define MAXA  512
#define NNB   2

#define THREADS    256
#define YHALF      60                          // y-extent per tile
#define PLANE_F    (YHALF * BOX)               // 7200 floats per half-plane
#define PLANE_F4   (PLANE_F / 4)               // 1800 float4
#define PLANE_B    (PLANE_F * 4)               // 28800 bytes
#define NTILES     (BT * BOX * 2)              // 10560 tiles
#define GRID       (148 * 3)                   // persistent CTAs (3 per SM)

// Dynamic smem layout: plane[2][PLANE_F] floats, then alist[MAXA] ints, acnt.
#define SMEM_BYTES (2 * PLANE_B + MAXA * 4 + 16)

// ---------------------------------------------------------------------------
// num_atoms dtype sniff: values in [1,512]. If int64 (LE), 32-bit word 1 is
// the zero high half of element 0; if int32, word 1 is num_atoms[1] >= 1.
// ---------------------------------------------------------------------------
__device__ __forceinline__ int get_natoms(const int* __restrict__ p, int bt) {
    return (p[1] == 0) ? p[2 * bt] : p[bt];
}

__device__ __forceinline__ uint32_t smem_u32(const void* p) {
    uint32_t a;
    asm("{ .reg .u64 t; cvta.to.shared.u64 t, %1; cvt.u32.u64 %0, t; }"
        : "=r"(a) : "l"(p));
    return a;
}

// ---------------------------------------------------------------------------
// Persistent fused kernel. Each CTA loops over tiles (bt, x, y-half) with two
// smem plane buffers: while buffer p's TMA bulk-store drains to gmem, the CTA
// zeroes/scans/scatters into buffer 1-p. Buffer reuse is guarded by
// cp.async.bulk.wait_group.read (the group issued 2 iterations ago was the
// last reader of this buffer). Output written exactly once, no global atomics.
// ---------------------------------------------------------------------------
__global__ void __launch_bounds__(THREADS) fused_kernel(
    const float* __restrict__ coords,    // [BT, 3*MAXA]
    const int* __restrict__ num_atoms,   // [BT] int32 (or int64, sniffed)
    float* __restrict__ out)             // [BT, VOL]
{
    extern __shared__ __align__(16) float smem[];
    float* planes = smem;                             // [2][PLANE_F]
    int*   alist  = (int*)(smem + 2 * PLANE_F);       // [MAXA]
    int*   acnt   = alist + MAXA;

    const int tid = threadIdx.x;
    int iter = 0;

    for (int t = blockIdx.x; t < NTILES; t += GRID, iter++) {
        const int p = iter & 1;
        float* plane = planes + p * PLANE_F;

        const int h  = t & 1;                 // y-half
        const int x  = (t >> 1) % BOX;
        const int bt = t / (BOX * 2);
        const int y0 = h * YHALF;

        const int na = get_natoms(num_atoms, bt);
        const float* cbt = coords + (long long)bt * (3 * MAXA);

        if (tid == 0) {
            // Ensure the TMA store that last READ this buffer (issued 2
            // iterations ago) has finished reading smem. Last iteration's
            // store (other buffer) stays in flight.
            if (iter >= 2)
                asm volatile("cp.async.bulk.wait_group.read 1;" ::: "memory");
            *acnt = 0;
        }
        __syncthreads();

        // Phase 1: zero this buffer AND scan atoms (independent work).
        float4* pl4 = (float4*)plane;
        const float4 zero4 = make_float4(0.f, 0.f, 0.f, 0.f);
        #pragma unroll
        for (int k = 0; k < 8; k++) {
            const int f4 = tid + k * THREADS;
            if (f4 < PLANE_F4) pl4[f4] = zero4;
        }
        for (int a = tid; a < na; a += THREADS) {
            const float ax = cbt[3 * a + 0];
            const float ay = cbt[3 * a + 1];
            const int cx = (int)floorf(ax);
            const int cy = (int)floorf(ay);
            const int ddx = x - cx;
            if (ddx >= -NNB && ddx <= NNB &&
                cy >= y0 - NNB && cy <= y0 + YHALF - 1 + NNB) {
                alist[atomicAdd(acnt, 1)] = a;
            }
        }
        __syncthreads();

        // Phase 2: scatter matched atoms into the buffer. Warp per atom;
        // lane l < 25 owns cell (cy + l/5 - 2, cz + l%5 - 2).
        const int cnt = *acnt;
        if (cnt > 0) {
            const int wid  = tid >> 5;
            const int lane = tid & 31;
            const float fx = (float)x;
            for (int i = wid; i < cnt; i += THREADS / 32) {
                const int a = alist[i];
                const float ax = cbt[3 * a + 0];
                const float ay = cbt[3 * a + 1];
                const float az = cbt[3 * a + 2];
                if (lane < 25) {
                    const int cy = (int)floorf(ay);
                    const int cz = (int)floorf(az);
                    const int iy = cy + lane / 5 - NNB;
                    const int iz = cz + lane % 5 - NNB;
                    if (iy >= y0 && iy < y0 + YHALF && (unsigned)iz < BOX) {
                        const float dx = fx - ax;
                        const float dy = (float)iy - ay;
                        const float dz = (float)iz - az;
                        const float v = __expf(-(dx * dx + dy * dy + dz * dz));
                        atomicAdd(&plane[(iy - y0) * BOX + iz], v);
                    }
                }
            }
        }
        __syncthreads();

        // Phase 3: issue the TMA bulk store for this buffer; do NOT wait.
        if (tid == 0) {
            float* dst = out + (long long)bt * VOL + x * (BOX * BOX) + y0 * BOX;
            asm volatile("fence.proxy.async.shared::cta;" ::: "memory");
            const uint32_t src = smem_u32(plane);
            asm volatile("cp.async.bulk.global.shared::cta.bulk_group [%0], [%1], %2;"
                         :: "l"(dst), "r"(src), "r"((uint32_t)PLANE_B) : "memory");
            asm volatile("cp.async.bulk.commit_group;" ::: "memory");
        }
    }

    // Drain all outstanding bulk stores before CTA exit.
    if (tid == 0)
        asm volatile("cp.async.bulk.wait_group 0;" ::: "memory");
}

// ---------------------------------------------------------------------------
// Opt into >48 KB dynamic smem once, at static-init time (host attribute set;
// no device allocation).
// ---------------------------------------------------------------------------
namespace {
struct AttrInit {
    AttrInit() {
        cudaFuncSetAttribute(fused_kernel,
                             cudaFuncAttributeMaxDynamicSharedMemorySize,
                             SMEM_BYTES);
    }
};
static AttrInit g_attr_init;
}  // namespace

// ---------------------------------------------------------------------------
extern "C" void kernel_launch(void* const* d_in, const int* in_sizes, int n_in,
                              void* d_out, int out_size) {
    const float* coords    = (const float*)d_in[0];  // float32 [4,11,1536]
    const int*   num_atoms = (const int*)d_in[1];    // int32/int64 [4,11]
    float*       out       = (float*)d_out;          // float32 [4,11,120,120,120]

    fused_kernel<<<GRID, THREADS, SMEM_BYTES>>>(coords, num_atoms, out);
}

// round 14
// speedup vs baseline: 1.0343x; 1.0343x over previous
#include <cuda_runtime.h>
#include <cstdint>

// Problem constants (match reference)
#define BOX   120
#define VOL   (BOX * BOX * BOX)       // 1,728,000
#define NTYPE 11
#define BATCH 4
#define BT    (BATCH * NTYPE)         // 44
#define MAXA  512
#define NNB   2

#define THREADS    256
#define YTILE      40                          // y-extent per CTA (3 tiles/plane)
#define NYT        (BOX / YTILE)               // 3
#define PLANE_F    (YTILE * BOX)               // 4800 floats per tile
#define PLANE_F4   (PLANE_F / 4)               // 1200 float4
#define PLANE_B    (PLANE_F * 4)               // 19200 bytes
#define KMAX       5                           // ceil(1200 / 256)
#define NBLOCKS    (BT * BOX * NYT)            // 15840 CTAs

// ---------------------------------------------------------------------------
// num_atoms dtype sniff: values in [1,512]. If int64 (LE), 32-bit word 1 is
// the zero high half of element 0; if int32, word 1 is num_atoms[1] >= 1.
// ---------------------------------------------------------------------------
__device__ __forceinline__ int get_natoms(const int* __restrict__ p, int bt) {
    return (p[1] == 0) ? p[2 * bt] : p[bt];
}

__device__ __forceinline__ uint32_t smem_u32(const void* p) {
    uint32_t a;
    asm("{ .reg .u64 t; cvta.to.shared.u64 t, %1; cvt.u32.u64 %0, t; }"
        : "=r"(a) : "l"(p));
    return a;
}

__device__ __forceinline__ void stcs4(float4* addr, float4 v) {
    asm volatile("st.global.cs.v4.f32 [%0], {%1, %2, %3, %4};"
                 :: "l"(addr), "f"(v.x), "f"(v.y), "f"(v.z), "f"(v.w) : "memory");
}

// ---------------------------------------------------------------------------
// Fused kernel (R12 structure, smaller tiles for higher CTA concurrency).
// One CTA of 256 threads per (bt, x, y-third). Zeroes its 40x120 tile in
// smem, scatters the few matching atoms via shared atomics, then streams the
// tile to gmem with a single cp.async.bulk (perfect 128B bursts, near-zero
// issue cost). ~11 CTAs/SM keep many TMA stores in flight -> smooth DRAM
// write stream. Output written exactly once; no global atomics.
// ---------------------------------------------------------------------------
__global__ void __launch_bounds__(THREADS) fused_kernel(
    const float* __restrict__ coords,    // [BT, 3*MAXA]
    const int* __restrict__ num_atoms,   // [BT] int32 (or int64, sniffed)
    float* __restrict__ out)             // [BT, VOL]
{
    __shared__ __align__(16) float plane[PLANE_F];   // 19.2 KB
    __shared__ unsigned short alist[MAXA];           // matched atom indices (1 KB)
    __shared__ int acnt;

    const int b  = blockIdx.x;
    const int s  = b % NYT;                  // y-third
    const int x  = (b / NYT) % BOX;
    const int bt = b / (BOX * NYT);
    const int y0 = s * YTILE;
    const int tid = threadIdx.x;

    const int na = get_natoms(num_atoms, bt);
    const float* cbt = coords + (long long)bt * (3 * MAXA);

    if (tid == 0) acnt = 0;
    __syncthreads();

    // Phase 1: zero the smem tile AND scan atoms (independent work, one phase).
    float4* pl4 = (float4*)plane;
    const float4 zero4 = make_float4(0.f, 0.f, 0.f, 0.f);
    #pragma unroll
    for (int k = 0; k < KMAX; k++) {
        const int f4 = tid + k * THREADS;
        if (f4 < PLANE_F4) pl4[f4] = zero4;
    }
    for (int a = tid; a < na; a += THREADS) {
        const float ax = cbt[3 * a + 0];
        const float ay = cbt[3 * a + 1];
        const int cx = (int)floorf(ax);
        const int cy = (int)floorf(ay);
        const int ddx = x - cx;
        if (ddx >= -NNB && ddx <= NNB &&
            cy >= y0 - NNB && cy <= y0 + YTILE - 1 + NNB) {
            alist[atomicAdd(&acnt, 1)] = (unsigned short)a;
        }
    }
    __syncthreads();

    const int cnt = acnt;
    float* dst = out + (long long)bt * VOL + x * (BOX * BOX) + y0 * BOX;

    if (cnt == 0) {
        // No atoms: stream zeros straight from registers (rare).
        #pragma unroll
        for (int k = 0; k < KMAX; k++) {
            const int f4 = tid + k * THREADS;
            if (f4 < PLANE_F4) stcs4((float4*)dst + f4, zero4);
        }
        return;
    }

    // Phase 2: scatter matched atoms into smem. Warp per atom; lane l < 25
    // owns cell (cy + l/5 - 2, cz + l%5 - 2).
    {
        const int wid  = tid >> 5;
        const int lane = tid & 31;
        const float fx = (float)x;
        for (int i = wid; i < cnt; i += THREADS / 32) {
            const int a = alist[i];
            const float ax = cbt[3 * a + 0];
            const float ay = cbt[3 * a + 1];
            const float az = cbt[3 * a + 2];
            if (lane < 25) {
                const int cy = (int)floorf(ay);
                const int cz = (int)floorf(az);
                const int iy = cy + lane / 5 - NNB;
                const int iz = cz + lane % 5 - NNB;
                if (iy >= y0 && iy < y0 + YTILE && (unsigned)iz < BOX) {
                    const float dx = fx - ax;
                    const float dy = (float)iy - ay;
                    const float dz = (float)iz - az;
                    const float v = __expf(-(dx * dx + dy * dy + dz * dz));
                    atomicAdd(&plane[(iy - y0) * BOX + iz], v);
                }
            }
        }
    }
    __syncthreads();

    // Phase 3: single TMA 1D bulk store smem -> gmem (19.2 KB, 16B-aligned).
    if (tid == 0) {
        asm volatile("fence.proxy.async.shared::cta;" ::: "memory");
        const uint32_t src = smem_u32(plane);
        asm volatile("cp.async.bulk.global.shared::cta.bulk_group [%0], [%1], %2;"
                     :: "l"(dst), "r"(src), "r"((uint32_t)PLANE_B) : "memory");
        asm volatile("cp.async.bulk.commit_group;" ::: "memory");
        asm volatile("cp.async.bulk.wait_group.read 0;" ::: "memory");
    }
}

// ---------------------------------------------------------------------------
extern "C" void kernel_launch(void* const* d_in, const int* in_sizes, int n_in,
                              void* d_out, int out_size) {
    const float* coords    = (const float*)d_in[0];  // float32 [4,11,1536]
    const int*   num_atoms = (const int*)d_in[1];    // int32/int64 [4,11]
    float*       out       = (float*)d_out;          // float32 [4,11,120,120,120]

    fused_kernel<<<NBLOCKS, THREADS>>>(coords, num_atoms, out);
}